// round 14
// baseline (speedup 1.0000x reference)
#include <cuda_runtime.h>
#include <cuda_bf16.h>
#include <cstdint>

// MetaDynamics via mma.sync bf16 tensor cores (compute_100-safe).
// e[p,h] = A_h + sum_{k<16} M[h,k] * X[k,p];  K=16 (8 b*x + 8 c*x^2), bias in epilogue.
//   iv = -0.5*log2e/wdt^2; b = -2*iv*cen; c = iv; A = sum iv*cen^2 + log2(hgt)
//   out[p] = sum_h 2^(e[p,h])
// bf16 hi/lo split: 3 MMAs per C tile (Xhi*Mhi + Xhi*Mlo + Xlo*Mhi), K=16 each.
// M row in smem: 32 bf16 = 64 B: [0,8)=b hi, [8,16)=c hi, [16,24)=b lo, [24,32)=c lo.
//
// R14: pre_hills ELIMINATED. Hill conversion is fused into the main kernel's
// double-buffer pipeline: per iteration, threads 0-127 issue raw cen/wdt/hgt
// loads for chunk u+1 FIRST (latency hidden under the chunk-u MMA loop), then
// convert + STS into the other buffer after the MMA loop, then the existing
// __syncthreads. 2 launches total (mma + tiny reduce).

#define N_HILLS   16384
#define N_POINTS  4096
#define N_CV      8

#define CHUNK     128
#define NCHUNKS   (N_HILLS / CHUNK)             // 128
#define NPTILES   (N_POINTS / 128)              // 32
#define UNITS     (NPTILES * NCHUNKS)           // 4096 (u = ptile*128 + chunk)
#define NCTAS     296
#define SLOTS     16

#define PITCH     80                            // 64B row + 16B pad (conflict-free LDSM)
#define BUF_DATA  (CHUNK * PITCH)               // 10240
#define BUF_A     (CHUNK * 4)                   // 512
#define BUF_BYTES (BUF_DATA + BUF_A)            // 10752

// ---- device-global scratch (zero-initialized; unwritten slots stay 0) ----
__device__ __align__(16) float g_part[N_POINTS * SLOTS];        // 256 KB

// ---- helpers ----
__device__ __forceinline__ uint32_t smem_u32(const void* p) {
    uint32_t a;
    asm("{ .reg .u64 t; cvta.to.shared.u64 t, %1; cvt.u32.u64 %0, t; }" : "=r"(a) : "l"(p));
    return a;
}
__device__ __forceinline__ float ex2f(float x) {
    float y; asm("ex2.approx.f32 %0, %1;" : "=f"(y) : "f"(x)); return y;
}
__device__ __forceinline__ float lg2f(float x) {
    float y; asm("lg2.approx.f32 %0, %1;" : "=f"(y) : "f"(x)); return y;
}

#define LDSM4(r, addr) \
    asm volatile("ldmatrix.sync.aligned.m8n8.x4.shared.b16 {%0,%1,%2,%3}, [%4];" \
        : "=r"((r)[0]), "=r"((r)[1]), "=r"((r)[2]), "=r"((r)[3]) : "r"(addr))

__device__ __forceinline__ void mma_acc(float c[4], const uint32_t a[4],
                                        uint32_t b0, uint32_t b1) {
    asm volatile(
        "mma.sync.aligned.m16n8k16.row.col.f32.bf16.bf16.f32 "
        "{%0,%1,%2,%3}, {%4,%5,%6,%7}, {%8,%9}, {%0,%1,%2,%3};"
        : "+f"(c[0]), "+f"(c[1]), "+f"(c[2]), "+f"(c[3])
        : "r"(a[0]), "r"(a[1]), "r"(a[2]), "r"(a[3]), "r"(b0), "r"(b1));
}

__device__ __forceinline__ void bf16_split(float v, __nv_bfloat16& hi, __nv_bfloat16& lo) {
    hi = __float2bfloat16_rn(v);
    lo = __float2bfloat16_rn(v - __bfloat162float(hi));
}
__device__ __forceinline__ uint32_t pack_bf(__nv_bfloat16 e0, __nv_bfloat16 e1) {
    uint32_t l = __bfloat16_as_ushort(e0), h = __bfloat16_as_ushort(e1);
    return l | (h << 16);
}

// ---- raw hill load (issue early; consumed after the MMA loop) ----
struct HillRaw { float4 c0, c1, w0, w1; float hg; };

__device__ __forceinline__ void load_hill(HillRaw& r, int h,
                                          const float* __restrict__ cen,
                                          const float* __restrict__ wdt,
                                          const float* __restrict__ hgt)
{
    r.c0 = *(const float4*)(cen + h * N_CV);
    r.c1 = *(const float4*)(cen + h * N_CV + 4);
    r.w0 = *(const float4*)(wdt + h * N_CV);
    r.w1 = *(const float4*)(wdt + h * N_CV + 4);
    r.hg = hgt[h];
}

// ---- convert one hill from registers into smem row (tid<128 only) ----
__device__ __forceinline__ void convert_store(char* sbuf, int tid, const HillRaw& r)
{
    const float NEG_HALF_LOG2E = -0.72134752044448170f;
    float cv[8] = {r.c0.x, r.c0.y, r.c0.z, r.c0.w, r.c1.x, r.c1.y, r.c1.z, r.c1.w};
    float wv[8] = {r.w0.x, r.w0.y, r.w0.z, r.w0.w, r.w1.x, r.w1.y, r.w1.z, r.w1.w};

    float A = lg2f(r.hg);
    __nv_bfloat16 bh[8], bl[8], ch_[8], cl[8];
    #pragma unroll
    for (int d = 0; d < N_CV; ++d) {
        float iv = __fdividef(NEG_HALF_LOG2E, wv[d] * wv[d]);
        float b  = -2.0f * iv * cv[d];
        A = fmaf(iv * cv[d], cv[d], A);
        bf16_split(b, bh[d], bl[d]);
        bf16_split(iv, ch_[d], cl[d]);
    }
    uint4 o0, o1, o2, o3;
    o0.x = pack_bf(bh[0], bh[1]);   o0.y = pack_bf(bh[2], bh[3]);
    o0.z = pack_bf(bh[4], bh[5]);   o0.w = pack_bf(bh[6], bh[7]);
    o1.x = pack_bf(ch_[0], ch_[1]); o1.y = pack_bf(ch_[2], ch_[3]);
    o1.z = pack_bf(ch_[4], ch_[5]); o1.w = pack_bf(ch_[6], ch_[7]);
    o2.x = pack_bf(bl[0], bl[1]);   o2.y = pack_bf(bl[2], bl[3]);
    o2.z = pack_bf(bl[4], bl[5]);   o2.w = pack_bf(bl[6], bl[7]);
    o3.x = pack_bf(cl[0], cl[1]);   o3.y = pack_bf(cl[2], cl[3]);
    o3.z = pack_bf(cl[4], cl[5]);   o3.w = pack_bf(cl[6], cl[7]);
    char* row = sbuf + tid * PITCH;
    *(uint4*)(row + 0)  = o0;
    *(uint4*)(row + 16) = o1;
    *(uint4*)(row + 32) = o2;
    *(uint4*)(row + 48) = o3;
    *(float*)(sbuf + BUF_DATA + tid * 4) = A;
}

__device__ __forceinline__ void build_A_frags(const float* __restrict__ col,
                                              int p0w, int g, int q,
                                              uint32_t Ahi[4], uint32_t Alo[4])
{
    const int rlo = p0w + g, rhi = rlo + 8;
    float2 xa = *(const float2*)(col + rlo * N_CV + 2 * q);
    float2 xb = *(const float2*)(col + rhi * N_CV + 2 * q);
    __nv_bfloat16 h0, l0, h1, l1;
    bf16_split(xa.x, h0, l0); bf16_split(xa.y, h1, l1);
    Ahi[0] = pack_bf(h0, h1);  Alo[0] = pack_bf(l0, l1);
    bf16_split(xb.x, h0, l0); bf16_split(xb.y, h1, l1);
    Ahi[1] = pack_bf(h0, h1);  Alo[1] = pack_bf(l0, l1);
    bf16_split(xa.x * xa.x, h0, l0); bf16_split(xa.y * xa.y, h1, l1);
    Ahi[2] = pack_bf(h0, h1);  Alo[2] = pack_bf(l0, l1);
    bf16_split(xb.x * xb.x, h0, l0); bf16_split(xb.y * xb.y, h1, l1);
    Ahi[3] = pack_bf(h0, h1);  Alo[3] = pack_bf(l0, l1);
}

__device__ __forceinline__ void flush(int pt, int p0w, int g, int q,
                                      float acc0, float acc1)
{
    acc0 += __shfl_xor_sync(0xFFFFFFFFu, acc0, 1);
    acc0 += __shfl_xor_sync(0xFFFFFFFFu, acc0, 2);
    acc1 += __shfl_xor_sync(0xFFFFFFFFu, acc1, 1);
    acc1 += __shfl_xor_sync(0xFFFFFFFFu, acc1, 2);
    if (q == 0) {
        const int slot = (int)blockIdx.x - ((pt * NCTAS) >> 5);   // c_first = floor(pt*296/32)
        g_part[(p0w + g) * SLOTS + slot]     = acc0;
        g_part[(p0w + g + 8) * SLOTS + slot] = acc1;
    }
}

__global__ void __launch_bounds__(256, 2)
metadyn_mma(const float* __restrict__ col,
            const float* __restrict__ cen,
            const float* __restrict__ wdt,
            const float* __restrict__ hgt)
{
    __shared__ __align__(16) char sbuf[2 * BUF_BYTES];

    const int tid  = threadIdx.x;
    const int lane = tid & 31;
    const int warp = tid >> 5;
    const int q    = lane & 3;
    const int g    = lane >> 2;
    const bool conv = (tid < CHUNK);

    const int u0 = (int)(((long long)blockIdx.x * UNITS) / NCTAS);
    const int u1 = (int)(((long long)(blockIdx.x + 1) * UNITS) / NCTAS);

    const uint32_t sb = smem_u32(sbuf);
    const uint32_t lanebase = (uint32_t)(((lane & 7) | ((lane >> 4) << 3)) * PITCH
                                         + ((lane >> 3) & 1) * 16);

    int cur_pt = u0 >> 7;
    int p0w = cur_pt * 128 + warp * 16;
    uint32_t Ahi[4], Alo[4];
    build_A_frags(col, p0w, g, q, Ahi, Alo);

    // Prologue: load + convert chunk(u0) into buffer 0.
    HillRaw raw;
    if (conv) {
        load_hill(raw, (u0 & (NCHUNKS - 1)) * CHUNK + tid, cen, wdt, hgt);
        convert_store(sbuf, tid, raw);
    }
    __syncthreads();

    float acc0 = 0.f, acc1 = 0.f;

    for (int u = u0; u < u1; ++u) {
        char* bufc = sbuf + ((u - u0) & 1) * BUF_BYTES;
        char* bufn = sbuf + ((u + 1 - u0) & 1) * BUF_BYTES;
        const uint32_t buf = sb + (uint32_t)((u - u0) & 1) * BUF_BYTES;
        const bool have_next = (u + 1 < u1);

        // Issue raw loads for chunk(u+1) NOW; latency hidden under the MMA loop.
        if (have_next && conv)
            load_hill(raw, ((u + 1) & (NCHUNKS - 1)) * CHUNK + tid, cen, wdt, hgt);

        const int pt = u >> 7;
        if (pt != cur_pt) {
            flush(cur_pt, p0w, g, q, acc0, acc1);
            acc0 = 0.f; acc1 = 0.f;
            cur_pt = pt;
            p0w = pt * 128 + warp * 16;
            build_A_frags(col, p0w, g, q, Ahi, Alo);
        }

        #pragma unroll
        for (int st = 0; st < CHUNK / 16; ++st) {      // 16 hills per step
            const uint32_t base = buf + (uint32_t)st * (16 * PITCH) + lanebase;
            uint32_t bh[4], bl[4];
            LDSM4(bh, base + 0);     // M hi: {n0 b0,b1, n1 b0,b1}
            LDSM4(bl, base + 32);    // M lo

            float C0[4] = {0.f, 0.f, 0.f, 0.f};
            float C1[4] = {0.f, 0.f, 0.f, 0.f};
            mma_acc(C0, Ahi, bh[0], bh[1]);
            mma_acc(C0, Ahi, bl[0], bl[1]);
            mma_acc(C0, Alo, bh[0], bh[1]);
            mma_acc(C1, Ahi, bh[2], bh[3]);
            mma_acc(C1, Ahi, bl[2], bl[3]);
            mma_acc(C1, Alo, bh[2], bh[3]);

            // bias (fp32) + exp2; C0 cols = hills st*16 + 2q,2q+1 ; C1 cols = +8
            const char* bias = bufc + BUF_DATA;
            float2 a0 = *(const float2*)(bias + (st * 16 + 2 * q) * 4);
            float2 a1 = *(const float2*)(bias + (st * 16 + 8 + 2 * q) * 4);
            acc0 += ex2f(C0[0] + a0.x) + ex2f(C0[1] + a0.y)
                  + ex2f(C1[0] + a1.x) + ex2f(C1[1] + a1.y);
            acc1 += ex2f(C0[2] + a0.x) + ex2f(C0[3] + a0.y)
                  + ex2f(C1[2] + a1.x) + ex2f(C1[3] + a1.y);
        }

        // Convert chunk(u+1) into the other buffer (its last readers finished
        // before the __syncthreads that ended iteration u-1).
        if (have_next && conv)
            convert_store(bufn, tid, raw);
        __syncthreads();   // conversion visible; all warps done with chunk u
    }

    flush(cur_pt, p0w, g, q, acc0, acc1);
}

// ===== final reduce over 16 slots per point =====
__global__ void __launch_bounds__(256)
metadyn_reduce(float* __restrict__ out)
{
    const int p = blockIdx.x * 256 + threadIdx.x;
    const float4* v = (const float4*)(g_part + p * SLOTS);
    float4 a = v[0], b = v[1], c = v[2], d = v[3];
    out[p] = (((a.x + a.y) + (a.z + a.w)) + ((b.x + b.y) + (b.z + b.w)))
           + (((c.x + c.y) + (c.z + c.w)) + ((d.x + d.y) + (d.z + d.w)));
}

extern "C" void kernel_launch(void* const* d_in, const int* in_sizes, int n_in,
                              void* d_out, int out_size)
{
    const float* col = (const float*)d_in[0];
    const float* cen = (const float*)d_in[1];
    const float* wdt = (const float*)d_in[2];
    const float* hgt = (const float*)d_in[3];
    float* out = (float*)d_out;

    metadyn_mma<<<NCTAS, 256>>>(col, cen, wdt, hgt);
    metadyn_reduce<<<N_POINTS / 256, 256>>>(out);
}

// round 15
// speedup vs baseline: 1.0008x; 1.0008x over previous
#include <cuda_runtime.h>
#include <cuda_bf16.h>
#include <cstdint>

// MetaDynamics via mma.sync bf16 tensor cores (compute_100-safe).
// e[p,h] = A_h + sum_{k<16} M[h,k] * X[k,p];  K=16 (8 b*x + 8 c*x^2), bias in epilogue.
//   iv = -0.5*log2e/wdt^2; b = -2*iv*cen; c = iv; A = sum iv*cen^2 + log2(hgt)
//   out[p] = sum_h 2^(e[p,h])
// bf16 hi/lo split: 3 MMAs per C tile (Xhi*Mhi + Xhi*Mlo + Xlo*Mhi), K=16 each.
// M row: 32 bf16 = 64 B: [0,8)=b hi, [8,16)=c hi, [16,24)=b lo, [24,32)=c lo.
//
// R15: SINGLE KERNEL. 296 CTAs @ 2/SM (= one full wave, all co-resident) with a
// software grid barrier (count + volatile generation; fences both sides):
//   phase 0: each CTA converts its ~56-hill range once -> g_M/g_A  (16K conversions)
//   barrier
//   phase 1: R13-verified MMA pipeline (cp.async double-buffer, register
//            accumulation per ptile, flush to 16 slots/point)
//   barrier
//   phase 2: each CTA reduces its ~14-point range (16 slots each) -> out
// Removes both tiny kernels (~4.7us each, launch-floor-bound) and their gaps.

#define N_HILLS   16384
#define N_POINTS  4096
#define N_CV      8

#define CHUNK     128
#define NCHUNKS   (N_HILLS / CHUNK)             // 128
#define NPTILES   (N_POINTS / 128)              // 32
#define UNITS     (NPTILES * NCHUNKS)           // 4096 (u = ptile*128 + chunk)
#define NCTAS     296
#define SLOTS     16

#define PITCH     80                            // 64B row + 16B pad (conflict-free LDSM)
#define BUF_DATA  (CHUNK * PITCH)               // 10240
#define BUF_A     (CHUNK * 4)                   // 512
#define BUF_BYTES (BUF_DATA + BUF_A)            // 10752

// ---- device-global scratch (zero-initialized; unwritten slots stay 0) ----
__device__ __align__(16) __nv_bfloat16 g_M[N_HILLS * 32];       // 1 MB
__device__ __align__(16) float g_A[N_HILLS];                    // 64 KB
__device__ __align__(16) float g_part[N_POINTS * SLOTS];        // 256 KB
__device__ int g_bar_count;
__device__ volatile unsigned g_bar_gen;

// ---- helpers ----
__device__ __forceinline__ uint32_t smem_u32(const void* p) {
    uint32_t a;
    asm("{ .reg .u64 t; cvta.to.shared.u64 t, %1; cvt.u32.u64 %0, t; }" : "=r"(a) : "l"(p));
    return a;
}
__device__ __forceinline__ float ex2f(float x) {
    float y; asm("ex2.approx.f32 %0, %1;" : "=f"(y) : "f"(x)); return y;
}
__device__ __forceinline__ void cp16(uint32_t dst, const void* src) {
    asm volatile("cp.async.cg.shared.global [%0], [%1], 16;" :: "r"(dst), "l"(src));
}
__device__ __forceinline__ void cp_commit() { asm volatile("cp.async.commit_group;" ::: "memory"); }
__device__ __forceinline__ void cp_wait1()  { asm volatile("cp.async.wait_group 1;" ::: "memory"); }
__device__ __forceinline__ void cp_wait0()  { asm volatile("cp.async.wait_group 0;" ::: "memory"); }

#define LDSM4(r, addr) \
    asm volatile("ldmatrix.sync.aligned.m8n8.x4.shared.b16 {%0,%1,%2,%3}, [%4];" \
        : "=r"((r)[0]), "=r"((r)[1]), "=r"((r)[2]), "=r"((r)[3]) : "r"(addr))

__device__ __forceinline__ void mma_acc(float c[4], const uint32_t a[4],
                                        uint32_t b0, uint32_t b1) {
    asm volatile(
        "mma.sync.aligned.m16n8k16.row.col.f32.bf16.bf16.f32 "
        "{%0,%1,%2,%3}, {%4,%5,%6,%7}, {%8,%9}, {%0,%1,%2,%3};"
        : "+f"(c[0]), "+f"(c[1]), "+f"(c[2]), "+f"(c[3])
        : "r"(a[0]), "r"(a[1]), "r"(a[2]), "r"(a[3]), "r"(b0), "r"(b1));
}

__device__ __forceinline__ void bf16_split(float v, __nv_bfloat16& hi, __nv_bfloat16& lo) {
    hi = __float2bfloat16_rn(v);
    lo = __float2bfloat16_rn(v - __bfloat162float(hi));
}
__device__ __forceinline__ uint32_t pack_bf(__nv_bfloat16 e0, __nv_bfloat16 e1) {
    uint32_t l = __bfloat16_as_ushort(e0), h = __bfloat16_as_ushort(e1);
    return l | (h << 16);
}

// ---- grid barrier: all NCTAS co-resident (296 = 2/SM x 148, single wave) ----
__device__ __forceinline__ void grid_bar(int tid)
{
    __syncthreads();                      // all warps of this CTA done with phase
    if (tid == 0) {
        unsigned my = g_bar_gen;          // volatile read (pre-arrival)
        __threadfence();                  // release: publish this CTA's writes
        int v = atomicAdd(&g_bar_count, 1);
        if (v == NCTAS - 1) {
            atomicExch(&g_bar_count, 0);
            __threadfence();
            g_bar_gen = my + 1;           // volatile store: open the gate
        } else {
            while (g_bar_gen == my) { }   // volatile spin (L2, not L1)
        }
        __threadfence();                  // acquire (also flushes L1)
    }
    __syncthreads();
}

// ===== phase 0: convert one hill -> g_M row + g_A =====
__device__ __forceinline__ void conv_hill(int h,
                                          const float* __restrict__ cen,
                                          const float* __restrict__ wdt,
                                          const float* __restrict__ hgt)
{
    const float NEG_HALF_LOG2E = -0.72134752044448170f;
    float4 c0 = *(const float4*)(cen + h * N_CV);
    float4 c1 = *(const float4*)(cen + h * N_CV + 4);
    float4 w0 = *(const float4*)(wdt + h * N_CV);
    float4 w1 = *(const float4*)(wdt + h * N_CV + 4);
    float cv[8] = {c0.x, c0.y, c0.z, c0.w, c1.x, c1.y, c1.z, c1.w};
    float wv[8] = {w0.x, w0.y, w0.z, w0.w, w1.x, w1.y, w1.z, w1.w};

    float A = log2f(hgt[h]);
    __nv_bfloat16 bh[8], bl[8], ch_[8], cl[8];
    #pragma unroll
    for (int d = 0; d < N_CV; ++d) {
        float iv = __fdividef(NEG_HALF_LOG2E, wv[d] * wv[d]);
        float b  = -2.0f * iv * cv[d];
        A = fmaf(iv * cv[d], cv[d], A);
        bf16_split(b, bh[d], bl[d]);
        bf16_split(iv, ch_[d], cl[d]);
    }
    uint4 o0, o1, o2, o3;
    o0.x = pack_bf(bh[0], bh[1]);   o0.y = pack_bf(bh[2], bh[3]);
    o0.z = pack_bf(bh[4], bh[5]);   o0.w = pack_bf(bh[6], bh[7]);
    o1.x = pack_bf(ch_[0], ch_[1]); o1.y = pack_bf(ch_[2], ch_[3]);
    o1.z = pack_bf(ch_[4], ch_[5]); o1.w = pack_bf(ch_[6], ch_[7]);
    o2.x = pack_bf(bl[0], bl[1]);   o2.y = pack_bf(bl[2], bl[3]);
    o2.z = pack_bf(bl[4], bl[5]);   o2.w = pack_bf(bl[6], bl[7]);
    o3.x = pack_bf(cl[0], cl[1]);   o3.y = pack_bf(cl[2], cl[3]);
    o3.z = pack_bf(cl[4], cl[5]);   o3.w = pack_bf(cl[6], cl[7]);
    uint4* dst = (uint4*)(g_M + h * 32);
    dst[0] = o0; dst[1] = o1; dst[2] = o2; dst[3] = o3;
    g_A[h] = A;
}

// ===== phase 1 helpers (R13-verified) =====
__device__ __forceinline__ void copy_chunk(uint32_t bufaddr, int hbase, int tid)
{
    const char* src = (const char*)g_M + (size_t)hbase * 64;
    #pragma unroll
    for (int k = 0; k < 2; ++k) {
        const int idx = tid + k * 256;
        const int row = idx >> 2;
        const int c   = idx & 3;
        cp16(bufaddr + row * PITCH + c * 16, src + row * 64 + c * 16);
    }
    if (tid < 32)
        cp16(bufaddr + BUF_DATA + tid * 16, (const char*)(g_A + hbase) + tid * 16);
}

__device__ __forceinline__ void build_A_frags(const float* __restrict__ col,
                                              int p0w, int g, int q,
                                              uint32_t Ahi[4], uint32_t Alo[4])
{
    const int rlo = p0w + g, rhi = rlo + 8;
    float2 xa = *(const float2*)(col + rlo * N_CV + 2 * q);
    float2 xb = *(const float2*)(col + rhi * N_CV + 2 * q);
    __nv_bfloat16 h0, l0, h1, l1;
    bf16_split(xa.x, h0, l0); bf16_split(xa.y, h1, l1);
    Ahi[0] = pack_bf(h0, h1);  Alo[0] = pack_bf(l0, l1);
    bf16_split(xb.x, h0, l0); bf16_split(xb.y, h1, l1);
    Ahi[1] = pack_bf(h0, h1);  Alo[1] = pack_bf(l0, l1);
    bf16_split(xa.x * xa.x, h0, l0); bf16_split(xa.y * xa.y, h1, l1);
    Ahi[2] = pack_bf(h0, h1);  Alo[2] = pack_bf(l0, l1);
    bf16_split(xb.x * xb.x, h0, l0); bf16_split(xb.y * xb.y, h1, l1);
    Ahi[3] = pack_bf(h0, h1);  Alo[3] = pack_bf(l0, l1);
}

__device__ __forceinline__ void flush(int pt, int p0w, int g, int q,
                                      float acc0, float acc1)
{
    acc0 += __shfl_xor_sync(0xFFFFFFFFu, acc0, 1);
    acc0 += __shfl_xor_sync(0xFFFFFFFFu, acc0, 2);
    acc1 += __shfl_xor_sync(0xFFFFFFFFu, acc1, 1);
    acc1 += __shfl_xor_sync(0xFFFFFFFFu, acc1, 2);
    if (q == 0) {
        const int slot = (int)blockIdx.x - ((pt * NCTAS) >> 5);   // c_first = floor(pt*296/32)
        g_part[(p0w + g) * SLOTS + slot]     = acc0;
        g_part[(p0w + g + 8) * SLOTS + slot] = acc1;
    }
}

__global__ void __launch_bounds__(256, 2)
metadyn_all(const float* __restrict__ col,
            const float* __restrict__ cen,
            const float* __restrict__ wdt,
            const float* __restrict__ hgt,
            float* __restrict__ out)
{
    __shared__ __align__(16) char sbuf[2 * BUF_BYTES];

    const int tid  = threadIdx.x;
    const int lane = tid & 31;
    const int warp = tid >> 5;
    const int q    = lane & 3;
    const int g    = lane >> 2;
    const int cta  = (int)blockIdx.x;

    // ---- phase 0: convert this CTA's hill range (once per hill globally) ----
    {
        const int h0 = (int)(((long long)cta * N_HILLS) / NCTAS);
        const int h1 = (int)(((long long)(cta + 1) * N_HILLS) / NCTAS);
        for (int h = h0 + tid; h < h1; h += 256)
            conv_hill(h, cen, wdt, hgt);
    }
    grid_bar(tid);

    // ---- phase 1: MMA over this CTA's unit range ----
    const int u0 = (int)(((long long)cta * UNITS) / NCTAS);
    const int u1 = (int)(((long long)(cta + 1) * UNITS) / NCTAS);

    const uint32_t sb = smem_u32(sbuf);
    const uint32_t lanebase = (uint32_t)(((lane & 7) | ((lane >> 4) << 3)) * PITCH
                                         + ((lane >> 3) & 1) * 16);

    int cur_pt = u0 >> 7;
    int p0w = cur_pt * 128 + warp * 16;
    uint32_t Ahi[4], Alo[4];
    build_A_frags(col, p0w, g, q, Ahi, Alo);

    copy_chunk(sb, (u0 & (NCHUNKS - 1)) * CHUNK, tid);
    cp_commit();

    float acc0 = 0.f, acc1 = 0.f;

    for (int u = u0; u < u1; ++u) {
        const uint32_t buf = sb + (uint32_t)((u - u0) & 1) * BUF_BYTES;
        if (u + 1 < u1) {
            copy_chunk(sb + (uint32_t)((u + 1 - u0) & 1) * BUF_BYTES,
                       ((u + 1) & (NCHUNKS - 1)) * CHUNK, tid);
            cp_commit();
            cp_wait1();
        } else {
            cp_wait0();
        }
        __syncthreads();

        const int pt = u >> 7;
        if (pt != cur_pt) {
            flush(cur_pt, p0w, g, q, acc0, acc1);
            acc0 = 0.f; acc1 = 0.f;
            cur_pt = pt;
            p0w = pt * 128 + warp * 16;
            build_A_frags(col, p0w, g, q, Ahi, Alo);
        }

        #pragma unroll
        for (int st = 0; st < CHUNK / 16; ++st) {      // 16 hills per step
            const uint32_t base = buf + (uint32_t)st * (16 * PITCH) + lanebase;
            uint32_t bh[4], bl[4];
            LDSM4(bh, base + 0);     // M hi: {n0 b0,b1, n1 b0,b1}
            LDSM4(bl, base + 32);    // M lo

            float C0[4] = {0.f, 0.f, 0.f, 0.f};
            float C1[4] = {0.f, 0.f, 0.f, 0.f};
            mma_acc(C0, Ahi, bh[0], bh[1]);
            mma_acc(C0, Ahi, bl[0], bl[1]);
            mma_acc(C0, Alo, bh[0], bh[1]);
            mma_acc(C1, Ahi, bh[2], bh[3]);
            mma_acc(C1, Ahi, bl[2], bl[3]);
            mma_acc(C1, Alo, bh[2], bh[3]);

            // bias (fp32) + exp2; C0 cols = hills st*16 + 2q,2q+1 ; C1 cols = +8
            const char* bias = sbuf + (buf - sb) + BUF_DATA;
            float2 a0 = *(const float2*)(bias + (st * 16 + 2 * q) * 4);
            float2 a1 = *(const float2*)(bias + (st * 16 + 8 + 2 * q) * 4);
            acc0 += ex2f(C0[0] + a0.x) + ex2f(C0[1] + a0.y)
                  + ex2f(C1[0] + a1.x) + ex2f(C1[1] + a1.y);
            acc1 += ex2f(C0[2] + a0.x) + ex2f(C0[3] + a0.y)
                  + ex2f(C1[2] + a1.x) + ex2f(C1[3] + a1.y);
        }
        __syncthreads();   // all warps done with this chunk before its buffer refills
    }

    flush(cur_pt, p0w, g, q, acc0, acc1);
    grid_bar(tid);

    // ---- phase 2: reduce this CTA's point range (16 slots each) ----
    {
        const int p0 = (int)(((long long)cta * N_POINTS) / NCTAS);
        const int p1 = (int)(((long long)(cta + 1) * N_POINTS) / NCTAS);
        for (int p = p0 + tid; p < p1; p += 256) {
            const float4* v = (const float4*)(g_part + p * SLOTS);
            float4 a = v[0], b = v[1], c = v[2], d = v[3];
            out[p] = (((a.x + a.y) + (a.z + a.w)) + ((b.x + b.y) + (b.z + b.w)))
                   + (((c.x + c.y) + (c.z + c.w)) + ((d.x + d.y) + (d.z + d.w)));
        }
    }
}

extern "C" void kernel_launch(void* const* d_in, const int* in_sizes, int n_in,
                              void* d_out, int out_size)
{
    const float* col = (const float*)d_in[0];
    const float* cen = (const float*)d_in[1];
    const float* wdt = (const float*)d_in[2];
    const float* hgt = (const float*)d_in[3];
    float* out = (float*)d_out;

    metadyn_all<<<NCTAS, 256>>>(col, cen, wdt, hgt, out);
}

// round 16
// speedup vs baseline: 1.1165x; 1.1156x over previous
#include <cuda_runtime.h>
#include <cuda_bf16.h>
#include <cstdint>

// MetaDynamics via mma.sync bf16 tensor cores (compute_100-safe).
// e[p,h] = A_h + sum_{k<16} M[h,k] * X[k,p];  K=16 (8 b*x + 8 c*x^2).
//   iv = -0.5*log2e/wdt^2; b = -2*iv*cen; c = iv; A = sum iv*cen^2 + log2(hgt)
//   out[p] = sum_h 2^(e[p,h])
// bf16 hi/lo split: 3 MMAs per C tile (Xhi*Mhi + Xhi*Mlo + Xlo*Mhi), K=16 each.
// M row: 32 bf16 = 64 B: [0,8)=b hi, [8,16)=c hi, [16,24)=b lo, [24,32)=c lo.
//
// R16 = R13 validated skeleton (3 kernels, persistent balanced mma, cp.async
// double-buffer, 16-slot partials; 35.0us) + bias folded into the MMA C-init:
// C0/C1 start at the fp32 bias instead of 0, deleting the 8 post-MMA FADDs per
// warp-step (67M thread-FADDs) and shortening the MMA->ex2 chain.

#define N_HILLS   16384
#define N_POINTS  4096
#define N_CV      8

#define CHUNK     128
#define NCHUNKS   (N_HILLS / CHUNK)             // 128
#define NPTILES   (N_POINTS / 128)              // 32
#define UNITS     (NPTILES * NCHUNKS)           // 4096 (u = ptile*128 + chunk)
#define NCTAS     296
#define SLOTS     16

#define PITCH     80                            // 64B row + 16B pad (conflict-free LDSM)
#define BUF_DATA  (CHUNK * PITCH)               // 10240
#define BUF_A     (CHUNK * 4)                   // 512
#define BUF_BYTES (BUF_DATA + BUF_A)            // 10752

// ---- device-global scratch (zero-initialized; unwritten slots stay 0) ----
__device__ __align__(16) __nv_bfloat16 g_M[N_HILLS * 32];       // 1 MB
__device__ __align__(16) float g_A[N_HILLS];                    // 64 KB
__device__ __align__(16) float g_part[N_POINTS * SLOTS];        // 256 KB

// ---- helpers ----
__device__ __forceinline__ uint32_t smem_u32(const void* p) {
    uint32_t a;
    asm("{ .reg .u64 t; cvta.to.shared.u64 t, %1; cvt.u32.u64 %0, t; }" : "=r"(a) : "l"(p));
    return a;
}
__device__ __forceinline__ float ex2f(float x) {
    float y; asm("ex2.approx.f32 %0, %1;" : "=f"(y) : "f"(x)); return y;
}
__device__ __forceinline__ void cp16(uint32_t dst, const void* src) {
    asm volatile("cp.async.cg.shared.global [%0], [%1], 16;" :: "r"(dst), "l"(src));
}
__device__ __forceinline__ void cp_commit() { asm volatile("cp.async.commit_group;" ::: "memory"); }
__device__ __forceinline__ void cp_wait1()  { asm volatile("cp.async.wait_group 1;" ::: "memory"); }
__device__ __forceinline__ void cp_wait0()  { asm volatile("cp.async.wait_group 0;" ::: "memory"); }

#define LDSM4(r, addr) \
    asm volatile("ldmatrix.sync.aligned.m8n8.x4.shared.b16 {%0,%1,%2,%3}, [%4];" \
        : "=r"((r)[0]), "=r"((r)[1]), "=r"((r)[2]), "=r"((r)[3]) : "r"(addr))

__device__ __forceinline__ void mma_acc(float c[4], const uint32_t a[4],
                                        uint32_t b0, uint32_t b1) {
    asm volatile(
        "mma.sync.aligned.m16n8k16.row.col.f32.bf16.bf16.f32 "
        "{%0,%1,%2,%3}, {%4,%5,%6,%7}, {%8,%9}, {%0,%1,%2,%3};"
        : "+f"(c[0]), "+f"(c[1]), "+f"(c[2]), "+f"(c[3])
        : "r"(a[0]), "r"(a[1]), "r"(a[2]), "r"(a[3]), "r"(b0), "r"(b1));
}

__device__ __forceinline__ void bf16_split(float v, __nv_bfloat16& hi, __nv_bfloat16& lo) {
    hi = __float2bfloat16_rn(v);
    lo = __float2bfloat16_rn(v - __bfloat162float(hi));
}
__device__ __forceinline__ uint32_t pack_bf(__nv_bfloat16 e0, __nv_bfloat16 e1) {
    uint32_t l = __bfloat16_as_ushort(e0), h = __bfloat16_as_ushort(e1);
    return l | (h << 16);
}

// ===== precompute: hill matrix M [16384][32] + bias A [16384]; 1 hill/thread =====
__global__ void __launch_bounds__(128)
pre_hills(const float* __restrict__ cen,
          const float* __restrict__ wdt,
          const float* __restrict__ hgt)
{
    const int h = blockIdx.x * 128 + threadIdx.x;
    const float NEG_HALF_LOG2E = -0.72134752044448170f;
    float4 c0 = *(const float4*)(cen + h * N_CV);
    float4 c1 = *(const float4*)(cen + h * N_CV + 4);
    float4 w0 = *(const float4*)(wdt + h * N_CV);
    float4 w1 = *(const float4*)(wdt + h * N_CV + 4);
    float cv[8] = {c0.x, c0.y, c0.z, c0.w, c1.x, c1.y, c1.z, c1.w};
    float wv[8] = {w0.x, w0.y, w0.z, w0.w, w1.x, w1.y, w1.z, w1.w};

    float A = log2f(hgt[h]);
    __nv_bfloat16 bh[8], bl[8], ch_[8], cl[8];
    #pragma unroll
    for (int d = 0; d < N_CV; ++d) {
        float iv = __fdividef(NEG_HALF_LOG2E, wv[d] * wv[d]);
        float b  = -2.0f * iv * cv[d];
        A = fmaf(iv * cv[d], cv[d], A);
        bf16_split(b, bh[d], bl[d]);
        bf16_split(iv, ch_[d], cl[d]);
    }
    uint4 o0, o1, o2, o3;
    o0.x = pack_bf(bh[0], bh[1]);   o0.y = pack_bf(bh[2], bh[3]);
    o0.z = pack_bf(bh[4], bh[5]);   o0.w = pack_bf(bh[6], bh[7]);
    o1.x = pack_bf(ch_[0], ch_[1]); o1.y = pack_bf(ch_[2], ch_[3]);
    o1.z = pack_bf(ch_[4], ch_[5]); o1.w = pack_bf(ch_[6], ch_[7]);
    o2.x = pack_bf(bl[0], bl[1]);   o2.y = pack_bf(bl[2], bl[3]);
    o2.z = pack_bf(bl[4], bl[5]);   o2.w = pack_bf(bl[6], bl[7]);
    o3.x = pack_bf(cl[0], cl[1]);   o3.y = pack_bf(cl[2], cl[3]);
    o3.z = pack_bf(cl[4], cl[5]);   o3.w = pack_bf(cl[6], cl[7]);
    uint4* dst = (uint4*)(g_M + h * 32);
    dst[0] = o0; dst[1] = o1; dst[2] = o2; dst[3] = o3;
    g_A[h] = A;
}

// ===== main tensor-core kernel (persistent, balanced, register-accumulated) =====
__device__ __forceinline__ void copy_chunk(uint32_t bufaddr, int hbase, int tid)
{
    const char* src = (const char*)g_M + (size_t)hbase * 64;
    #pragma unroll
    for (int k = 0; k < 2; ++k) {
        const int idx = tid + k * 256;
        const int row = idx >> 2;
        const int c   = idx & 3;
        cp16(bufaddr + row * PITCH + c * 16, src + row * 64 + c * 16);
    }
    if (tid < 32)
        cp16(bufaddr + BUF_DATA + tid * 16, (const char*)(g_A + hbase) + tid * 16);
}

__device__ __forceinline__ void build_A_frags(const float* __restrict__ col,
                                              int p0w, int g, int q,
                                              uint32_t Ahi[4], uint32_t Alo[4])
{
    const int rlo = p0w + g, rhi = rlo + 8;
    float2 xa = *(const float2*)(col + rlo * N_CV + 2 * q);
    float2 xb = *(const float2*)(col + rhi * N_CV + 2 * q);
    __nv_bfloat16 h0, l0, h1, l1;
    bf16_split(xa.x, h0, l0); bf16_split(xa.y, h1, l1);
    Ahi[0] = pack_bf(h0, h1);  Alo[0] = pack_bf(l0, l1);
    bf16_split(xb.x, h0, l0); bf16_split(xb.y, h1, l1);
    Ahi[1] = pack_bf(h0, h1);  Alo[1] = pack_bf(l0, l1);
    bf16_split(xa.x * xa.x, h0, l0); bf16_split(xa.y * xa.y, h1, l1);
    Ahi[2] = pack_bf(h0, h1);  Alo[2] = pack_bf(l0, l1);
    bf16_split(xb.x * xb.x, h0, l0); bf16_split(xb.y * xb.y, h1, l1);
    Ahi[3] = pack_bf(h0, h1);  Alo[3] = pack_bf(l0, l1);
}

__device__ __forceinline__ void flush(int pt, int p0w, int g, int q,
                                      float acc0, float acc1)
{
    acc0 += __shfl_xor_sync(0xFFFFFFFFu, acc0, 1);
    acc0 += __shfl_xor_sync(0xFFFFFFFFu, acc0, 2);
    acc1 += __shfl_xor_sync(0xFFFFFFFFu, acc1, 1);
    acc1 += __shfl_xor_sync(0xFFFFFFFFu, acc1, 2);
    if (q == 0) {
        const int slot = (int)blockIdx.x - ((pt * NCTAS) >> 5);   // c_first = floor(pt*296/32)
        g_part[(p0w + g) * SLOTS + slot]     = acc0;
        g_part[(p0w + g + 8) * SLOTS + slot] = acc1;
    }
}

__global__ void __launch_bounds__(256, 2)
metadyn_mma(const float* __restrict__ col)
{
    __shared__ __align__(16) char sbuf[2 * BUF_BYTES];

    const int tid  = threadIdx.x;
    const int lane = tid & 31;
    const int warp = tid >> 5;
    const int q    = lane & 3;
    const int g    = lane >> 2;

    const int u0 = (int)(((long long)blockIdx.x * UNITS) / NCTAS);
    const int u1 = (int)(((long long)(blockIdx.x + 1) * UNITS) / NCTAS);

    const uint32_t sb = smem_u32(sbuf);
    const uint32_t lanebase = (uint32_t)(((lane & 7) | ((lane >> 4) << 3)) * PITCH
                                         + ((lane >> 3) & 1) * 16);

    int cur_pt = u0 >> 7;
    int p0w = cur_pt * 128 + warp * 16;
    uint32_t Ahi[4], Alo[4];
    build_A_frags(col, p0w, g, q, Ahi, Alo);

    copy_chunk(sb, (u0 & (NCHUNKS - 1)) * CHUNK, tid);
    cp_commit();

    float acc0 = 0.f, acc1 = 0.f;

    for (int u = u0; u < u1; ++u) {
        const uint32_t buf = sb + (uint32_t)((u - u0) & 1) * BUF_BYTES;
        if (u + 1 < u1) {
            copy_chunk(sb + (uint32_t)((u + 1 - u0) & 1) * BUF_BYTES,
                       ((u + 1) & (NCHUNKS - 1)) * CHUNK, tid);
            cp_commit();
            cp_wait1();
        } else {
            cp_wait0();
        }
        __syncthreads();

        const int pt = u >> 7;
        if (pt != cur_pt) {
            flush(cur_pt, p0w, g, q, acc0, acc1);
            acc0 = 0.f; acc1 = 0.f;
            cur_pt = pt;
            p0w = pt * 128 + warp * 16;
            build_A_frags(col, p0w, g, q, Ahi, Alo);
        }

        #pragma unroll
        for (int st = 0; st < CHUNK / 16; ++st) {      // 16 hills per step
            const uint32_t base = buf + (uint32_t)st * (16 * PITCH) + lanebase;
            uint32_t bh[4], bl[4];
            LDSM4(bh, base + 0);     // M hi: {n0 b0,b1, n1 b0,b1}
            LDSM4(bl, base + 32);    // M lo

            // bias (fp32) folded into the MMA C-init: cols depend only on hill,
            // rows g and g+8 share it -> {x, y, x, y}
            const char* bias = sbuf + (buf - sb) + BUF_DATA;
            float2 a0 = *(const float2*)(bias + (st * 16 + 2 * q) * 4);
            float2 a1 = *(const float2*)(bias + (st * 16 + 8 + 2 * q) * 4);
            float C0[4] = {a0.x, a0.y, a0.x, a0.y};
            float C1[4] = {a1.x, a1.y, a1.x, a1.y};

            mma_acc(C0, Ahi, bh[0], bh[1]);
            mma_acc(C0, Ahi, bl[0], bl[1]);
            mma_acc(C0, Alo, bh[0], bh[1]);
            mma_acc(C1, Ahi, bh[2], bh[3]);
            mma_acc(C1, Ahi, bl[2], bl[3]);
            mma_acc(C1, Alo, bh[2], bh[3]);

            acc0 += ex2f(C0[0]) + ex2f(C0[1]) + ex2f(C1[0]) + ex2f(C1[1]);
            acc1 += ex2f(C0[2]) + ex2f(C0[3]) + ex2f(C1[2]) + ex2f(C1[3]);
        }
        __syncthreads();   // all warps done with this chunk before its buffer refills
    }

    flush(cur_pt, p0w, g, q, acc0, acc1);
}

// ===== final reduce over 16 slots per point =====
__global__ void __launch_bounds__(256)
metadyn_reduce(float* __restrict__ out)
{
    const int p = blockIdx.x * 256 + threadIdx.x;
    const float4* v = (const float4*)(g_part + p * SLOTS);
    float4 a = v[0], b = v[1], c = v[2], d = v[3];
    out[p] = (((a.x + a.y) + (a.z + a.w)) + ((b.x + b.y) + (b.z + b.w)))
           + (((c.x + c.y) + (c.z + c.w)) + ((d.x + d.y) + (d.z + d.w)));
}

extern "C" void kernel_launch(void* const* d_in, const int* in_sizes, int n_in,
                              void* d_out, int out_size)
{
    const float* col = (const float*)d_in[0];
    const float* cen = (const float*)d_in[1];
    const float* wdt = (const float*)d_in[2];
    const float* hgt = (const float*)d_in[3];
    float* out = (float*)d_out;

    pre_hills<<<N_HILLS / 128, 128>>>(cen, wdt, hgt);
    metadyn_mma<<<NCTAS, 256>>>(col);
    metadyn_reduce<<<N_POINTS / 256, 256>>>(out);
}